// round 3
// baseline (speedup 1.0000x reference)
#include <cuda_runtime.h>
#include <math.h>

#define DIMV       512
#define HEADS      8
#define DIM_KEY    32
#define NUM_KEYS   256
#define TOPK       16
#define TOKENS     1024
#define FULLMASK   0xffffffffu

// scratch (device globals; no allocs)
__device__ float g_q[TOKENS * DIMV];                    // 2 MB
__device__ float g_sim[HEADS * TOKENS * NUM_KEYS];      // 8 MB
__device__ float g_wdT[DIMV * NUM_KEYS];                // 512 KB  wdown[:256]^T
__device__ float g_D[TOKENS * NUM_KEYS];                // 1 MB    q @ wdown^T
__device__ float g_S[TOKENS * NUM_KEYS];                // 1 MB    scatter weights

// ---------------------------------------------------------------------------
// Double-buffered SGEMM: C[M,N] = A[M,K] @ B[K,N]  (row-major), optional scale.
// BM in {32,64}, BN=64, BK=16, 256 threads, per-thread (BM/16) x 4 outputs.
// ---------------------------------------------------------------------------
template<int BM, int M, int N, int K, bool SCALE>
__global__ void sgemm_db(const float* __restrict__ A,
                         const float* __restrict__ B,
                         float* __restrict__ C)
{
    const int TM = BM / 16;           // 4 or 2
    const int NTA = BM * 16 / 256;    // A floats per thread per tile
    __shared__ float As[2][16][BM];
    __shared__ float Bs[2][16][64];

    int tid = threadIdx.x;
    int tx = tid & 15;
    int ty = tid >> 4;
    int m0 = blockIdx.y * BM;
    int n0 = blockIdx.x * 64;

    // load mappings
    int ak = tid & 15;                // A k within tile
    int bc = tid & 63;                // B col
    int bk = tid >> 6;                // B k base (stride 4)

    float areg[NTA], breg[4];
#pragma unroll
    for (int i = 0; i < NTA; i++) {
        int r = ty + i * 16;
        areg[i] = A[(size_t)(m0 + r) * K + ak];
    }
#pragma unroll
    for (int i = 0; i < 4; i++)
        breg[i] = B[(size_t)(bk + i * 4) * N + n0 + bc];

    float cr[TM][4];
#pragma unroll
    for (int i = 0; i < TM; i++)
#pragma unroll
        for (int j = 0; j < 4; j++) cr[i][j] = 0.0f;

    int buf = 0;
    const int NT = K / 16;
#pragma unroll 1
    for (int kt = 0; kt < NT; kt++) {
        // store staged tile
#pragma unroll
        for (int i = 0; i < NTA; i++)
            As[buf][ak][ty + i * 16] = areg[i];
#pragma unroll
        for (int i = 0; i < 4; i++)
            Bs[buf][bk + i * 4][bc] = breg[i];
        __syncthreads();

        // prefetch next tile into registers (latency hidden by compute)
        if (kt + 1 < NT) {
            int k0 = (kt + 1) * 16;
#pragma unroll
            for (int i = 0; i < NTA; i++) {
                int r = ty + i * 16;
                areg[i] = A[(size_t)(m0 + r) * K + k0 + ak];
            }
#pragma unroll
            for (int i = 0; i < 4; i++)
                breg[i] = B[(size_t)(k0 + bk + i * 4) * N + n0 + bc];
        }

#pragma unroll
        for (int k = 0; k < 16; k++) {
            float a[TM], b[4];
#pragma unroll
            for (int i = 0; i < TM; i++) a[i] = As[buf][k][ty * TM + i];
            float4 b4 = *reinterpret_cast<const float4*>(&Bs[buf][k][tx * 4]);
            b[0] = b4.x; b[1] = b4.y; b[2] = b4.z; b[3] = b4.w;
#pragma unroll
            for (int i = 0; i < TM; i++)
#pragma unroll
                for (int j = 0; j < 4; j++) cr[i][j] += a[i] * b[j];
        }
        buf ^= 1;
    }

    const float scale = SCALE ? 0.99999500003749981f : 1.0f;
#pragma unroll
    for (int i = 0; i < TM; i++) {
        int row = m0 + ty * TM + i;
        float4 f;
        f.x = cr[i][0] * scale; f.y = cr[i][1] * scale;
        f.z = cr[i][2] * scale; f.w = cr[i][3] * scale;
        *reinterpret_cast<float4*>(&C[(size_t)row * N + n0 + tx * 4]) = f;
    }
}

// ---------------------------------------------------------------------------
// Transpose wdown[0:256][512] -> g_wdT[512][256]
// ---------------------------------------------------------------------------
__global__ void transpose_wd(const float* __restrict__ wd)
{
    __shared__ float t[32][33];
    int d0 = blockIdx.x * 32;
    int e0 = blockIdx.y * 32;
    int tx = threadIdx.x, ty = threadIdx.y;   // 32 x 8
#pragma unroll
    for (int i = 0; i < 4; i++)
        t[ty + i * 8][tx] = wd[(size_t)(e0 + ty + i * 8) * DIMV + d0 + tx];
    __syncthreads();
#pragma unroll
    for (int i = 0; i < 4; i++)
        g_wdT[(size_t)(d0 + ty + i * 8) * NUM_KEYS + e0 + tx] = t[tx][ty + i * 8];
}

// ---------------------------------------------------------------------------
// sim kernel: g_sim[h][t][k] = dot(q[t, h*32:+32], keys[h][k][0][:])
// ---------------------------------------------------------------------------
__global__ void sim_kernel(const float* __restrict__ keys)
{
    int h  = blockIdx.y;
    int t0 = blockIdx.x * 64;
    int tid = threadIdx.x;

    __shared__ float Ks[DIM_KEY][NUM_KEYS];
    __shared__ float Qs[DIM_KEY][64];

    {
        const float4* kp = reinterpret_cast<const float4*>(
            keys + (size_t)((h * NUM_KEYS + tid) * 2) * DIM_KEY);
#pragma unroll
        for (int i = 0; i < 8; i++) {
            float4 f = kp[i];
            Ks[4 * i + 0][tid] = f.x;
            Ks[4 * i + 1][tid] = f.y;
            Ks[4 * i + 2][tid] = f.z;
            Ks[4 * i + 3][tid] = f.w;
        }
    }
    {
        int tl = tid & 63;
        int d0 = (tid >> 6) * 8;
        const float* qp = g_q + (size_t)(t0 + tl) * DIMV + h * DIM_KEY + d0;
        float4 f0 = *reinterpret_cast<const float4*>(qp);
        float4 f1 = *reinterpret_cast<const float4*>(qp + 4);
        Qs[d0 + 0][tl] = f0.x; Qs[d0 + 1][tl] = f0.y;
        Qs[d0 + 2][tl] = f0.z; Qs[d0 + 3][tl] = f0.w;
        Qs[d0 + 4][tl] = f1.x; Qs[d0 + 5][tl] = f1.y;
        Qs[d0 + 6][tl] = f1.z; Qs[d0 + 7][tl] = f1.w;
    }
    __syncthreads();

    int kg = tid & 15;
    int tg = tid >> 4;
    float acc[4][16];
#pragma unroll
    for (int i = 0; i < 4; i++)
#pragma unroll
        for (int j = 0; j < 16; j++) acc[i][j] = 0.0f;

#pragma unroll
    for (int d = 0; d < DIM_KEY; d++) {
        float4 qv = *reinterpret_cast<const float4*>(&Qs[d][tg * 4]);
        float q4[4] = {qv.x, qv.y, qv.z, qv.w};
        float kv[16];
#pragma unroll
        for (int jj = 0; jj < 4; jj++) {
            float4 kk = *reinterpret_cast<const float4*>(&Ks[d][kg * 16 + jj * 4]);
            kv[jj * 4 + 0] = kk.x; kv[jj * 4 + 1] = kk.y;
            kv[jj * 4 + 2] = kk.z; kv[jj * 4 + 3] = kk.w;
        }
#pragma unroll
        for (int i = 0; i < 4; i++)
#pragma unroll
            for (int j = 0; j < 16; j++) acc[i][j] += q4[i] * kv[j];
    }

#pragma unroll
    for (int i = 0; i < 4; i++) {
        int t = t0 + tg * 4 + i;
        float* op = g_sim + ((size_t)h * TOKENS + t) * NUM_KEYS + kg * 16;
#pragma unroll
        for (int jj = 0; jj < 4; jj++) {
            float4 f;
            f.x = acc[i][jj * 4 + 0]; f.y = acc[i][jj * 4 + 1];
            f.z = acc[i][jj * 4 + 2]; f.w = acc[i][jj * 4 + 3];
            *reinterpret_cast<float4*>(op + jj * 4) = f;
        }
    }
}

// ---------------------------------------------------------------------------
// Selection kernel: top16(sim) -> combined top16 -> softmax -> gelu(D) ->
// scatter into S row. One block per token, one warp per head.
// ---------------------------------------------------------------------------
__device__ __forceinline__ float gelu_tanh(float x) {
    float x3 = x * x * x;
    float t = tanhf(0.7978845608028654f * (x + 0.044715f * x3));
    return 0.5f * x * (1.0f + t);
}

__device__ __forceinline__ void warp_top16(float* val, int lane,
                                           float* out_v, int* out_i)
{
#pragma unroll
    for (int r = 0; r < TOPK; r++) {
        float bv = val[0]; int bs = 0;
#pragma unroll
        for (int s = 1; s < 8; s++)
            if (val[s] > bv) { bv = val[s]; bs = s; }
        int bp = lane + (bs << 5);
#pragma unroll
        for (int off = 16; off > 0; off >>= 1) {
            float ov = __shfl_xor_sync(FULLMASK, bv, off);
            int   op = __shfl_xor_sync(FULLMASK, bp, off);
            if (ov > bv || (ov == bv && op < bp)) { bv = ov; bp = op; }
        }
        out_v[r] = bv;
        out_i[r] = bp;
        if ((bp & 31) == lane) {
            int ws = bp >> 5;
#pragma unroll
            for (int s = 0; s < 8; s++)
                if (s == ws) val[s] = -INFINITY;
        }
    }
}

__global__ void select_kernel()
{
    int t = blockIdx.x;
    int tid = threadIdx.x;
    int w = tid >> 5;     // head
    int lane = tid & 31;

    __shared__ float sS[NUM_KEYS];
    __shared__ float v0s[HEADS][TOPK];
    __shared__ float i0s[HEADS][TOPK];

    sS[tid] = 0.0f;
    __syncthreads();

    // sim row for this head
    float val[8];
    {
        const float* simrow = g_sim + ((size_t)w * TOKENS + t) * NUM_KEYS;
#pragma unroll
        for (int s = 0; s < 8; s++)
            val[s] = simrow[lane + (s << 5)];
    }

    float v0[TOPK]; int i0[TOPK];
    warp_top16(val, lane, v0, i0);
    if (lane == 0) {
#pragma unroll
        for (int r = 0; r < TOPK; r++) {
            v0s[w][r] = v0[r];
            i0s[w][r] = (float)i0[r];
        }
    }
    __syncwarp();

    float val2[8];
#pragma unroll
    for (int s = 0; s < 8; s++) {
        int p = lane + (s << 5);
        val2[s] = v0s[w][p >> 4] + i0s[w][p & 15];
    }

    float scf[TOPK]; int pk[TOPK];
    warp_top16(val2, lane, scf, pk);

    float myscf = -INFINITY; int mypk = 0;
#pragma unroll
    for (int r = 0; r < TOPK; r++)
        if (lane == r) { myscf = scf[r]; mypk = pk[r]; }

    float m = scf[0];
#pragma unroll
    for (int r = 1; r < TOPK; r++) m = fmaxf(m, scf[r]);
    float mye = expf(myscf - m);
    float esum = mye;
#pragma unroll
    for (int off = 16; off > 0; off >>= 1)
        esum += __shfl_xor_sync(FULLMASK, esum, off);

    if (lane < TOPK) {
        float dv = g_D[(size_t)t * NUM_KEYS + mypk];
        float g = gelu_tanh(dv) * (mye / esum);
        atomicAdd(&sS[mypk], g);
    }
    __syncthreads();

    g_S[(size_t)t * NUM_KEYS + tid] = sS[tid];
}

// ---------------------------------------------------------------------------
extern "C" void kernel_launch(void* const* d_in, const int* in_sizes, int n_in,
                              void* d_out, int out_size)
{
    const float* x     = (const float*)d_in[0];
    const float* w_q   = (const float*)d_in[1];
    const float* keys  = (const float*)d_in[2];
    const float* wdown = (const float*)d_in[3];
    const float* wup   = (const float*)d_in[4];
    float* out = (float*)d_out;

    int tokens = in_sizes[0] / DIMV;   // 1024

    float* d_q;   cudaGetSymbolAddress((void**)&d_q,   g_q);
    float* d_wdT; cudaGetSymbolAddress((void**)&d_wdT, g_wdT);
    float* d_D;   cudaGetSymbolAddress((void**)&d_D,   g_D);
    float* d_S;   cudaGetSymbolAddress((void**)&d_S,   g_S);

    // G1: q = (x @ w_q) * bn_scale       [1024,512] = [1024,512]@[512,512]
    {
        dim3 grid(DIMV / 64, tokens / 64);
        sgemm_db<64, TOKENS, DIMV, DIMV, true><<<grid, 256>>>(x, w_q, d_q);
    }
    // transpose wdown[:256] -> wdT [512,256]
    {
        dim3 grid(DIMV / 32, NUM_KEYS / 32);
        transpose_wd<<<grid, dim3(32, 8)>>>(wdown);
    }
    // sim
    {
        dim3 grid(tokens / 64, HEADS);
        sim_kernel<<<grid, 256>>>(keys);
    }
    // G2: D = q @ wdT                    [1024,256] = [1024,512]@[512,256]
    {
        dim3 grid(NUM_KEYS / 64, tokens / 32);
        sgemm_db<32, TOKENS, NUM_KEYS, DIMV, false><<<grid, 256>>>(d_q, d_wdT, d_D);
    }
    // selection + scatter into S
    select_kernel<<<tokens, 256>>>();

    // G3: out = S @ wup[:256]            [1024,512] = [1024,256]@[256,512]
    {
        dim3 grid(DIMV / 64, tokens / 64);
        sgemm_db<64, TOKENS, DIMV, NUM_KEYS, false><<<grid, 256>>>(d_S, wup, out);
    }
}

// round 4
// speedup vs baseline: 1.2966x; 1.2966x over previous
#include <cuda_runtime.h>
#include <math.h>

#define DIMV       512
#define HEADS      8
#define DIM_KEY    32
#define NUM_KEYS   256
#define TOPK       16
#define TOKENS     1024
#define FULLMASK   0xffffffffu

// scratch (device globals; no allocs)
__device__ float g_q[TOKENS * DIMV];                    // 2 MB
__device__ float g_sim[HEADS * TOKENS * NUM_KEYS];      // 8 MB
__device__ float g_wdT[DIMV * NUM_KEYS];                // 512 KB
__device__ float g_D[TOKENS * NUM_KEYS];                // 1 MB
__device__ float g_S[TOKENS * NUM_KEYS];                // 1 MB

// ---------------------------------------------------------------------------
// Register-pipelined SGEMM block. C[.,N] tile at (m0,n0).
// BM = TM*16, BN = 64, BK = 16, 256 threads, per-thread TM x 4 outputs.
// smem layout: As[2][16][BM+4] then Bs[2][16][64].
// ---------------------------------------------------------------------------
template<int TM, int N, int K, bool SCALE>
__device__ __forceinline__ void sgemm_block(
    const float* __restrict__ A, const float* __restrict__ B,
    float* __restrict__ C, int m0, int n0, char* smem_raw)
{
    const int BM = TM * 16;
    const int ASTR = BM + 4;
    typedef float AsT[16][ASTR];
    typedef float BsT[16][64];
    AsT* As = (AsT*)smem_raw;
    BsT* Bs = (BsT*)(smem_raw + 2 * 16 * ASTR * sizeof(float));

    int tid = threadIdx.x;
    int tx = tid & 15;
    int ty = tid >> 4;

    float acc[TM][4];
#pragma unroll
    for (int i = 0; i < TM; i++)
#pragma unroll
        for (int j = 0; j < 4; j++) acc[i][j] = 0.0f;

    // staging registers
    float arg[TM == 4 ? 4 : 2];
    float4 brg;

    // load mappings
    const int arow4 = tid >> 2, akq4 = (tid & 3) * 4;   // TM==4
    const int arow2 = tid >> 3, akq2 = (tid & 7) * 2;   // TM==2
    const int bkrow = tid >> 4, bnq = (tid & 15) * 4;

    // initial global loads (tile 0)
    if (TM == 4) {
        float4 v = *reinterpret_cast<const float4*>(
            &A[(size_t)(m0 + arow4) * K + akq4]);
        arg[0] = v.x; arg[1] = v.y; arg[2] = v.z; arg[3] = v.w;
    } else {
        float2 v = *reinterpret_cast<const float2*>(
            &A[(size_t)(m0 + arow2) * K + akq2]);
        arg[0] = v.x; arg[1] = v.y;
    }
    brg = *reinterpret_cast<const float4*>(&B[(size_t)bkrow * N + n0 + bnq]);

    int buf = 0;
    const int NT = K / 16;
#pragma unroll 1
    for (int kt = 0; kt < NT; kt++) {
        // commit staged tile to smem
        if (TM == 4) {
#pragma unroll
            for (int i = 0; i < 4; i++) As[buf][akq4 + i][arow4] = arg[i];
        } else {
#pragma unroll
            for (int i = 0; i < 2; i++) As[buf][akq2 + i][arow2] = arg[i];
        }
        *reinterpret_cast<float4*>(&Bs[buf][bkrow][bnq]) = brg;
        __syncthreads();

        // prefetch next tile (latency hidden under compute)
        if (kt + 1 < NT) {
            int k0 = (kt + 1) * 16;
            if (TM == 4) {
                float4 v = *reinterpret_cast<const float4*>(
                    &A[(size_t)(m0 + arow4) * K + k0 + akq4]);
                arg[0] = v.x; arg[1] = v.y; arg[2] = v.z; arg[3] = v.w;
            } else {
                float2 v = *reinterpret_cast<const float2*>(
                    &A[(size_t)(m0 + arow2) * K + k0 + akq2]);
                arg[0] = v.x; arg[1] = v.y;
            }
            brg = *reinterpret_cast<const float4*>(
                &B[(size_t)(k0 + bkrow) * N + n0 + bnq]);
        }

        // compute with register-pipelined fragments
        float ac[TM];
        float4 bc;
        if (TM == 4) {
            float4 a4 = *reinterpret_cast<const float4*>(&As[buf][0][ty * 4]);
            ac[0] = a4.x; ac[1] = a4.y; ac[2] = a4.z; ac[3] = a4.w;
        } else {
            float2 a2 = *reinterpret_cast<const float2*>(&As[buf][0][ty * 2]);
            ac[0] = a2.x; ac[1] = a2.y;
        }
        bc = *reinterpret_cast<const float4*>(&Bs[buf][0][tx * 4]);

#pragma unroll
        for (int k = 0; k < 16; k++) {
            float an[TM]; float4 bn;
            if (k < 15) {
                if (TM == 4) {
                    float4 a4 = *reinterpret_cast<const float4*>(&As[buf][k + 1][ty * 4]);
                    an[0] = a4.x; an[1] = a4.y; an[2] = a4.z; an[3] = a4.w;
                } else {
                    float2 a2 = *reinterpret_cast<const float2*>(&As[buf][k + 1][ty * 2]);
                    an[0] = a2.x; an[1] = a2.y;
                }
                bn = *reinterpret_cast<const float4*>(&Bs[buf][k + 1][tx * 4]);
            }
#pragma unroll
            for (int i = 0; i < TM; i++) {
                acc[i][0] += ac[i] * bc.x;
                acc[i][1] += ac[i] * bc.y;
                acc[i][2] += ac[i] * bc.z;
                acc[i][3] += ac[i] * bc.w;
            }
            if (k < 15) {
#pragma unroll
                for (int i = 0; i < TM; i++) ac[i] = an[i];
                bc = bn;
            }
        }
        buf ^= 1;
    }

    const float scale = SCALE ? 0.99999500003749981f : 1.0f;
#pragma unroll
    for (int i = 0; i < TM; i++) {
        int row = m0 + ty * TM + i;
        float4 f;
        f.x = acc[i][0] * scale; f.y = acc[i][1] * scale;
        f.z = acc[i][2] * scale; f.w = acc[i][3] * scale;
        *reinterpret_cast<float4*>(&C[(size_t)row * N + n0 + tx * 4]) = f;
    }
}

// ---------------------------------------------------------------------------
// K1: G1 (q = x @ w_q, scaled) on blocks 0..127; transpose wdown on 128..255.
// ---------------------------------------------------------------------------
__global__ void __launch_bounds__(256)
k1_fused(const float* __restrict__ x, const float* __restrict__ wq,
         const float* __restrict__ wdown)
{
    __shared__ __align__(16) char smem[2 * 16 * 68 * 4 + 2 * 16 * 64 * 4];
    int bid = blockIdx.x;
    if (bid < 128) {
        int mb = bid >> 3, nb = bid & 7;
        sgemm_block<4, DIMV, DIMV, true>(x, wq, g_q, mb * 64, nb * 64, smem);
    } else {
        int b = bid - 128;
        int d0 = (b & 15) * 32;
        int e0 = (b >> 4) * 32;
        float (*t)[33] = (float(*)[33])smem;
        int tx = threadIdx.x & 31, ty = threadIdx.x >> 5;  // 32 x 8
#pragma unroll
        for (int i = 0; i < 4; i++)
            t[ty + i * 8][tx] = wdown[(size_t)(e0 + ty + i * 8) * DIMV + d0 + tx];
        __syncthreads();
#pragma unroll
        for (int i = 0; i < 4; i++)
            g_wdT[(size_t)(d0 + ty + i * 8) * NUM_KEYS + e0 + tx] = t[tx][ty + i * 8];
    }
}

// ---------------------------------------------------------------------------
// K2: G2 (D = q @ wdT) on blocks 0..127; sim on 128..255.
// ---------------------------------------------------------------------------
__global__ void __launch_bounds__(256)
k2_fused(const float* __restrict__ keys)
{
    __shared__ __align__(16) char smem[DIM_KEY * NUM_KEYS * 4 + DIM_KEY * 64 * 4];
    int bid = blockIdx.x;
    int tid = threadIdx.x;

    if (bid < 128) {
        // G2: M=1024 (32 m-tiles of 32), N=256 (4 n-tiles of 64)
        int mb = bid >> 2, nb = bid & 3;
        sgemm_block<2, NUM_KEYS, DIMV, false>(g_q, g_wdT, g_D, mb * 32, nb * 64, smem);
        return;
    }

    // sim
    int b = bid - 128;
    int t0 = (b & 15) * 64;
    int h = b >> 4;

    float (*Ks)[NUM_KEYS] = (float(*)[NUM_KEYS])smem;
    float (*Qs)[64] = (float(*)[64])(smem + DIM_KEY * NUM_KEYS * 4);

    {
        const float4* kp = reinterpret_cast<const float4*>(
            keys + (size_t)((h * NUM_KEYS + tid) * 2) * DIM_KEY);
#pragma unroll
        for (int i = 0; i < 8; i++) {
            float4 f = kp[i];
            Ks[4 * i + 0][tid] = f.x;
            Ks[4 * i + 1][tid] = f.y;
            Ks[4 * i + 2][tid] = f.z;
            Ks[4 * i + 3][tid] = f.w;
        }
    }
    {
        int tl = tid & 63;
        int d0 = (tid >> 6) * 8;
        const float* qp = g_q + (size_t)(t0 + tl) * DIMV + h * DIM_KEY + d0;
        float4 f0 = *reinterpret_cast<const float4*>(qp);
        float4 f1 = *reinterpret_cast<const float4*>(qp + 4);
        Qs[d0 + 0][tl] = f0.x; Qs[d0 + 1][tl] = f0.y;
        Qs[d0 + 2][tl] = f0.z; Qs[d0 + 3][tl] = f0.w;
        Qs[d0 + 4][tl] = f1.x; Qs[d0 + 5][tl] = f1.y;
        Qs[d0 + 6][tl] = f1.z; Qs[d0 + 7][tl] = f1.w;
    }
    __syncthreads();

    int kg = tid & 15;
    int tg = tid >> 4;
    float acc[4][16];
#pragma unroll
    for (int i = 0; i < 4; i++)
#pragma unroll
        for (int j = 0; j < 16; j++) acc[i][j] = 0.0f;

#pragma unroll
    for (int d = 0; d < DIM_KEY; d++) {
        float4 qv = *reinterpret_cast<const float4*>(&Qs[d][tg * 4]);
        float q4[4] = {qv.x, qv.y, qv.z, qv.w};
        float kv[16];
#pragma unroll
        for (int jj = 0; jj < 4; jj++) {
            float4 kk = *reinterpret_cast<const float4*>(&Ks[d][kg * 16 + jj * 4]);
            kv[jj * 4 + 0] = kk.x; kv[jj * 4 + 1] = kk.y;
            kv[jj * 4 + 2] = kk.z; kv[jj * 4 + 3] = kk.w;
        }
#pragma unroll
        for (int i = 0; i < 4; i++)
#pragma unroll
            for (int j = 0; j < 16; j++) acc[i][j] += q4[i] * kv[j];
    }

#pragma unroll
    for (int i = 0; i < 4; i++) {
        int t = t0 + tg * 4 + i;
        float* op = g_sim + ((size_t)h * TOKENS + t) * NUM_KEYS + kg * 16;
#pragma unroll
        for (int jj = 0; jj < 4; jj++) {
            float4 f;
            f.x = acc[i][jj * 4 + 0]; f.y = acc[i][jj * 4 + 1];
            f.z = acc[i][jj * 4 + 2]; f.w = acc[i][jj * 4 + 3];
            *reinterpret_cast<float4*>(op + jj * 4) = f;
        }
    }
}

// ---------------------------------------------------------------------------
// K3: selection: top16(sim) -> combined top16 -> softmax -> gelu(D) -> S row.
// ---------------------------------------------------------------------------
__device__ __forceinline__ float gelu_tanh(float x) {
    float x3 = x * x * x;
    float t = tanhf(0.7978845608028654f * (x + 0.044715f * x3));
    return 0.5f * x * (1.0f + t);
}

__device__ __forceinline__ void warp_top16(float* val, int lane,
                                           float* out_v, int* out_i)
{
#pragma unroll
    for (int r = 0; r < TOPK; r++) {
        float bv = val[0]; int bs = 0;
#pragma unroll
        for (int s = 1; s < 8; s++)
            if (val[s] > bv) { bv = val[s]; bs = s; }
        int bp = lane + (bs << 5);
#pragma unroll
        for (int off = 16; off > 0; off >>= 1) {
            float ov = __shfl_xor_sync(FULLMASK, bv, off);
            int   op = __shfl_xor_sync(FULLMASK, bp, off);
            if (ov > bv || (ov == bv && op < bp)) { bv = ov; bp = op; }
        }
        out_v[r] = bv;
        out_i[r] = bp;
        if ((bp & 31) == lane) {
            int ws = bp >> 5;
#pragma unroll
            for (int s = 0; s < 8; s++)
                if (s == ws) val[s] = -INFINITY;
        }
    }
}

__global__ void __launch_bounds__(256) select_kernel()
{
    int t = blockIdx.x;
    int tid = threadIdx.x;
    int w = tid >> 5;
    int lane = tid & 31;

    __shared__ float sS[NUM_KEYS];
    __shared__ float v0s[HEADS][TOPK];
    __shared__ float i0s[HEADS][TOPK];

    sS[tid] = 0.0f;
    __syncthreads();

    float val[8];
    {
        const float* simrow = g_sim + ((size_t)w * TOKENS + t) * NUM_KEYS;
#pragma unroll
        for (int s = 0; s < 8; s++)
            val[s] = simrow[lane + (s << 5)];
    }

    float v0[TOPK]; int i0[TOPK];
    warp_top16(val, lane, v0, i0);
    if (lane == 0) {
#pragma unroll
        for (int r = 0; r < TOPK; r++) {
            v0s[w][r] = v0[r];
            i0s[w][r] = (float)i0[r];
        }
    }
    __syncwarp();

    float val2[8];
#pragma unroll
    for (int s = 0; s < 8; s++) {
        int p = lane + (s << 5);
        val2[s] = v0s[w][p >> 4] + i0s[w][p & 15];
    }

    float scf[TOPK]; int pk[TOPK];
    warp_top16(val2, lane, scf, pk);

    float myscf = -INFINITY; int mypk = 0;
#pragma unroll
    for (int r = 0; r < TOPK; r++)
        if (lane == r) { myscf = scf[r]; mypk = pk[r]; }

    float m = scf[0];
#pragma unroll
    for (int r = 1; r < TOPK; r++) m = fmaxf(m, scf[r]);
    float mye = expf(myscf - m);
    float esum = mye;
#pragma unroll
    for (int off = 16; off > 0; off >>= 1)
        esum += __shfl_xor_sync(FULLMASK, esum, off);

    if (lane < TOPK) {
        float dv = g_D[(size_t)t * NUM_KEYS + mypk];
        float g = gelu_tanh(dv) * (mye / esum);
        atomicAdd(&sS[mypk], g);
    }
    __syncthreads();

    g_S[(size_t)t * NUM_KEYS + tid] = sS[tid];
}

// ---------------------------------------------------------------------------
// K4: out = S @ wup[:256]
// ---------------------------------------------------------------------------
__global__ void __launch_bounds__(256)
k4_gemm(const float* __restrict__ wup, float* __restrict__ out)
{
    __shared__ __align__(16) char smem[2 * 16 * 68 * 4 + 2 * 16 * 64 * 4];
    int bid = blockIdx.x;
    int mb = bid >> 3, nb = bid & 7;
    sgemm_block<4, DIMV, NUM_KEYS, false>(g_S, wup, out, mb * 64, nb * 64, smem);
}

// ---------------------------------------------------------------------------
extern "C" void kernel_launch(void* const* d_in, const int* in_sizes, int n_in,
                              void* d_out, int out_size)
{
    const float* x     = (const float*)d_in[0];
    const float* w_q   = (const float*)d_in[1];
    const float* keys  = (const float*)d_in[2];
    const float* wdown = (const float*)d_in[3];
    const float* wup   = (const float*)d_in[4];
    float* out = (float*)d_out;

    k1_fused<<<256, 256>>>(x, w_q, wdown);
    k2_fused<<<256, 256>>>(keys);
    select_kernel<<<TOKENS, 256>>>();
    k4_gemm<<<128, 256>>>(wup, out);
}